// round 12
// baseline (speedup 1.0000x reference)
#include <cuda_runtime.h>
#include <math.h>
#include <stdint.h>

// Problem constants
#define Bv     32
#define Lv     2048
#define Dv     256
#define Hv     512
#define TWOH   1024
#define INNERv 1024
#define Mv     65536      // B*L tokens
#define NCH    32         // scan chunks
#define CHL    64         // L / NCH
#define BH     (Bv * Hv)  // 16384
#define BH4    (BH / 4)   // 4096

// ---------------- scratch (static device globals; no allocation) -------------
__device__ float g_xz[67108864];    // [M, 2H]  (xh | z)
__device__ float g_xc[33554432];    // [M, H]
__device__ float g_gates[67108864]; // [M, 2H]  (rec | inp)
__device__ float g_u[33554432];     // [M, H]  silu(z)*h
__device__ float g_y[16777216];     // [M, D]
__device__ float g_hs[16777216];    // [M, D]
__device__ float g_ff1[67108864];   // [M, INNER]
__device__ float g_ff[16777216];    // [M, D]
__device__ float g_cA[524288];      // [NCH][B*H]  (coalesced layout)
__device__ float g_cB[524288];      // [NCH][B*H]
__device__ float g_hin[524288];     // [NCH][B*H]

__device__ __forceinline__ float sigmoidf_(float x) { return 1.0f / (1.0f + __expf(-x)); }
__device__ __forceinline__ float siluf(float x)     { return x / (1.0f + __expf(-x)); }

// Split fp32 into tf32 hi + tf32 lo (3xTF32 trick): v ~= hi + lo to ~2^-21.
__device__ __forceinline__ void split_tf32(float v, uint32_t& h, uint32_t& l) {
    asm("cvt.rna.tf32.f32 %0, %1;" : "=r"(h) : "f"(v));
    float r = v - __uint_as_float(h);
    asm("cvt.rna.tf32.f32 %0, %1;" : "=r"(l) : "f"(r));
}

__device__ __forceinline__ void mma_tf32(float* c, const uint32_t* a, const uint32_t* b) {
    asm volatile(
        "mma.sync.aligned.m16n8k8.row.col.f32.tf32.tf32.f32 "
        "{%0,%1,%2,%3}, {%4,%5,%6,%7}, {%8,%9}, {%0,%1,%2,%3};"
        : "+f"(c[0]), "+f"(c[1]), "+f"(c[2]), "+f"(c[3])
        : "r"(a[0]), "r"(a[1]), "r"(a[2]), "r"(a[3]), "r"(b[0]), "r"(b[1]));
}

// ---------------- tensor-core GEMM: C = A[MxK] @ W[KxN] (+bias, act) ---------
// 128x64 block, BK=16, 256 threads (4x2 warps), warp does 32x32 via m16n8k8.
// 3xTF32 compensated: acc += Ah*Bh + Ah*Bl + Al*Bh (~fp32 accuracy).
// 2-stage smem double buffering + register prefetch: ONE sync per K-tile.
// __launch_bounds__(256, 2): cap 128 regs -> 2 CTAs/SM so one CTA's MMA work
// shadows the other CTA's barrier/prefetch phases.
#define SMSA 136            // A row stride (136 mod 32 == 8 -> conflict-free)
#define SMSB 72             // B row stride ( 72 mod 32 == 8 -> conflict-free)
#define A_WORDS (16 * SMSA) // 2176
#define B_WORDS (16 * SMSB) // 1152
#define STAGE_WORDS (2 * A_WORDS + 2 * B_WORDS)          // AsH, AsL, BsH, BsL
#define GEMM_SMEM_BYTES (2 * STAGE_WORDS * 4)            // 53248

template <int ACT>  // 0 = none, 1 = silu
__global__ __launch_bounds__(256, 2) void gemm_tc(const float* __restrict__ A,
                                                  const float* __restrict__ W,
                                                  const float* __restrict__ bias,
                                                  float* __restrict__ C,
                                                  int M, int N, int K) {
    extern __shared__ uint32_t smbuf[];

    const int tid  = threadIdx.x;
    const int warp = tid >> 5;
    const int lane = tid & 31;
    const int wm = warp >> 1;           // 0..3
    const int wn = warp & 1;            // 0..1
    const int m0 = blockIdx.y * 128;
    const int n0 = blockIdx.x * 64;

    float acc[2][4][4];
#pragma unroll
    for (int i = 0; i < 2; i++)
#pragma unroll
        for (int j = 0; j < 4; j++)
#pragma unroll
            for (int k = 0; k < 4; k++) acc[i][j][k] = 0.0f;

    const int ar = lane >> 2;   // 0..7 (m within fragment)
    const int ac = lane & 3;    // 0..3 (k within fragment)
    const int br = lane & 3;    // 0..3 (k)
    const int bc = lane >> 2;   // 0..7 (n)

    // Global-load mapping
    const int arow = tid >> 2;            // 0..63 (second half adds 64)
    const int acol = (tid & 3) * 4;       // 0,4,8,12
    const int brow = tid >> 4;            // 0..15
    const int bcol = (tid & 15) * 4;      // 0..60
    const float* Aptr = A + (size_t)(m0 + arow) * K + acol;
    const float* Bptr = W + (size_t)brow * N + n0 + bcol;
    const size_t Aoff1 = (size_t)64 * K;

    const int T = K >> 4;                 // number of 16-wide K tiles

    auto store_tile = [&](uint32_t* S, const float4& ca0, const float4& ca1,
                          const float4& cb) {
        uint32_t* AsH = S;
        uint32_t* AsL = S + A_WORDS;
        uint32_t* BsH = S + 2 * A_WORDS;
        uint32_t* BsL = S + 2 * A_WORDS + B_WORDS;
        uint32_t h, l;
        split_tf32(ca0.x, h, l); AsH[(acol + 0) * SMSA + arow] = h; AsL[(acol + 0) * SMSA + arow] = l;
        split_tf32(ca0.y, h, l); AsH[(acol + 1) * SMSA + arow] = h; AsL[(acol + 1) * SMSA + arow] = l;
        split_tf32(ca0.z, h, l); AsH[(acol + 2) * SMSA + arow] = h; AsL[(acol + 2) * SMSA + arow] = l;
        split_tf32(ca0.w, h, l); AsH[(acol + 3) * SMSA + arow] = h; AsL[(acol + 3) * SMSA + arow] = l;
        split_tf32(ca1.x, h, l); AsH[(acol + 0) * SMSA + arow + 64] = h; AsL[(acol + 0) * SMSA + arow + 64] = l;
        split_tf32(ca1.y, h, l); AsH[(acol + 1) * SMSA + arow + 64] = h; AsL[(acol + 1) * SMSA + arow + 64] = l;
        split_tf32(ca1.z, h, l); AsH[(acol + 2) * SMSA + arow + 64] = h; AsL[(acol + 2) * SMSA + arow + 64] = l;
        split_tf32(ca1.w, h, l); AsH[(acol + 3) * SMSA + arow + 64] = h; AsL[(acol + 3) * SMSA + arow + 64] = l;
        split_tf32(cb.x, h, l);  BsH[brow * SMSB + bcol + 0] = h; BsL[brow * SMSB + bcol + 0] = l;
        split_tf32(cb.y, h, l);  BsH[brow * SMSB + bcol + 1] = h; BsL[brow * SMSB + bcol + 1] = l;
        split_tf32(cb.z, h, l);  BsH[brow * SMSB + bcol + 2] = h; BsL[brow * SMSB + bcol + 2] = l;
        split_tf32(cb.w, h, l);  BsH[brow * SMSB + bcol + 3] = h; BsL[brow * SMSB + bcol + 3] = l;
    };

    // Prologue: tile0 -> stage0; prefetch tile1 into regs.
    float4 pa0 = *(const float4*)(Aptr);
    float4 pa1 = *(const float4*)(Aptr + Aoff1);
    float4 pb  = *(const float4*)(Bptr);
    store_tile(smbuf, pa0, pa1, pb);
    if (T > 1) {
        pa0 = *(const float4*)(Aptr + 16);
        pa1 = *(const float4*)(Aptr + Aoff1 + 16);
        pb  = *(const float4*)(Bptr + (size_t)16 * N);
    }
    __syncthreads();

    for (int t = 0; t < T; t++) {
        uint32_t* S = smbuf + (t & 1) * STAGE_WORDS;
        if (t + 1 < T) {
            store_tile(smbuf + ((t + 1) & 1) * STAGE_WORDS, pa0, pa1, pb);
            if (t + 2 < T) {
                const int koff = (t + 2) * 16;
                pa0 = *(const float4*)(Aptr + koff);
                pa1 = *(const float4*)(Aptr + Aoff1 + koff);
                pb  = *(const float4*)(Bptr + (size_t)koff * N);
            }
        }

        const uint32_t* AsH = S;
        const uint32_t* AsL = S + A_WORDS;
        const uint32_t* BsH = S + 2 * A_WORDS;
        const uint32_t* BsL = S + 2 * A_WORDS + B_WORDS;
#pragma unroll
        for (int kk = 0; kk < 16; kk += 8) {
            uint32_t aH[2][4], aL[2][4];
#pragma unroll
            for (int mt = 0; mt < 2; mt++) {
                const int rb = wm * 32 + mt * 16;
                aH[mt][0] = AsH[(kk + ac    ) * SMSA + rb + ar];
                aH[mt][1] = AsH[(kk + ac    ) * SMSA + rb + ar + 8];
                aH[mt][2] = AsH[(kk + ac + 4) * SMSA + rb + ar];
                aH[mt][3] = AsH[(kk + ac + 4) * SMSA + rb + ar + 8];
                aL[mt][0] = AsL[(kk + ac    ) * SMSA + rb + ar];
                aL[mt][1] = AsL[(kk + ac    ) * SMSA + rb + ar + 8];
                aL[mt][2] = AsL[(kk + ac + 4) * SMSA + rb + ar];
                aL[mt][3] = AsL[(kk + ac + 4) * SMSA + rb + ar + 8];
            }
            uint32_t bH[4][2], bL[4][2];
#pragma unroll
            for (int nt = 0; nt < 4; nt++) {
                const int col = wn * 32 + nt * 8 + bc;
                bH[nt][0] = BsH[(kk + br    ) * SMSB + col];
                bH[nt][1] = BsH[(kk + br + 4) * SMSB + col];
                bL[nt][0] = BsL[(kk + br    ) * SMSB + col];
                bL[nt][1] = BsL[(kk + br + 4) * SMSB + col];
            }
#pragma unroll
            for (int mt = 0; mt < 2; mt++)
#pragma unroll
                for (int nt = 0; nt < 4; nt++) {
                    mma_tf32(acc[mt][nt], aH[mt], bH[nt]);
                    mma_tf32(acc[mt][nt], aH[mt], bL[nt]);
                    mma_tf32(acc[mt][nt], aL[mt], bH[nt]);
                }
        }
        __syncthreads();
    }

    // Epilogue
#pragma unroll
    for (int mt = 0; mt < 2; mt++) {
#pragma unroll
        for (int nt = 0; nt < 4; nt++) {
            const int row = m0 + wm * 32 + mt * 16 + (lane >> 2);
            const int col = n0 + wn * 32 + nt * 8 + (lane & 3) * 2;
            float b0 = 0.f, b1 = 0.f;
            if (bias) { b0 = bias[col]; b1 = bias[col + 1]; }
            float v0 = acc[mt][nt][0] + b0;
            float v1 = acc[mt][nt][1] + b1;
            float v2 = acc[mt][nt][2] + b0;
            float v3 = acc[mt][nt][3] + b1;
            if (ACT == 1) { v0 = siluf(v0); v1 = siluf(v1); v2 = siluf(v2); v3 = siluf(v3); }
            *(float2*)&C[(size_t)row * N + col]       = make_float2(v0, v1);
            *(float2*)&C[(size_t)(row + 8) * N + col] = make_float2(v2, v3);
        }
    }
}

// ------- depthwise causal conv (K=4) + bias + silu, 4 channels/thread --------
__global__ void conv_silu_kernel(const float* __restrict__ conv_w,
                                 const float* __restrict__ conv_b) {
    size_t idx = (size_t)blockIdx.x * blockDim.x + threadIdx.x;   // over M*H/4
    if (idx >= (size_t)Mv * Hv / 4) return;
    const int c = (int)((idx * 4) % Hv);          // channel base (multiple of 4)
    const size_t row = (idx * 4) / Hv;            // b*L + t
    const int t = (int)(row % Lv);

    float4 w0 = *(const float4*)&conv_w[(c + 0) * 4];
    float4 w1 = *(const float4*)&conv_w[(c + 1) * 4];
    float4 w2 = *(const float4*)&conv_w[(c + 2) * 4];
    float4 w3 = *(const float4*)&conv_w[(c + 3) * 4];
    float4 bb = *(const float4*)&conv_b[c];
    float a0 = bb.x, a1 = bb.y, a2 = bb.z, a3 = bb.w;

#pragma unroll
    for (int j = 0; j < 4; j++) {
        const int tt = t - 3 + j;
        if (tt >= 0) {
            float4 xv = *(const float4*)&g_xz[(row - 3 + j) * TWOH + c];
            a0 = fmaf(((const float*)&w0)[j], xv.x, a0);
            a1 = fmaf(((const float*)&w1)[j], xv.y, a1);
            a2 = fmaf(((const float*)&w2)[j], xv.z, a2);
            a3 = fmaf(((const float*)&w3)[j], xv.w, a3);
        }
    }
    float4 o;
    o.x = siluf(a0); o.y = siluf(a1); o.z = siluf(a2); o.w = siluf(a3);
    *(float4*)&g_xc[row * Hv + c] = o;
}

// ---------------- fused alpha/beta' + chunked scan (4 ch/thread) -------------
__device__ __forceinline__ float alpha_of(float rec, float sp) {
    return __expf(-sp * sigmoidf_(rec));
}
__device__ __forceinline__ float bp_of(float alpha, float inp, float xc) {
    return sqrtf(1.0f - alpha * alpha + 1e-8f) * sigmoidf_(inp) * xc;
}

__global__ void scan_pass1(const float* __restrict__ Lambda) {
    const int gid = blockIdx.x * blockDim.x + threadIdx.x;   // over BH4*NCH
    if (gid >= BH4 * NCH) return;
    const int q  = gid % BH4;          // 4-channel group within B*H
    const int ch = gid / BH4;
    const int b = (q * 4) / Hv, c = (q * 4) % Hv;
    float4 lam = *(const float4*)&Lambda[c];
    float sp0 = log1pf(__expf(lam.x)), sp1 = log1pf(__expf(lam.y));
    float sp2 = log1pf(__expf(lam.z)), sp3 = log1pf(__expf(lam.w));
    size_t grow = (size_t)(b * Lv + ch * CHL);
    size_t base_g = grow * TWOH + c;
    size_t base_x = grow * Hv + c;
    float A0 = 1.f, A1 = 1.f, A2 = 1.f, A3 = 1.f;
    float B0 = 0.f, B1 = 0.f, B2 = 0.f, B3 = 0.f;
#pragma unroll 4
    for (int i = 0; i < CHL; i++) {
        float4 rec = *(const float4*)&g_gates[base_g];
        float4 inp = *(const float4*)&g_gates[base_g + Hv];
        float4 xc  = *(const float4*)&g_xc[base_x];
        float a0 = alpha_of(rec.x, sp0), a1 = alpha_of(rec.y, sp1);
        float a2 = alpha_of(rec.z, sp2), a3 = alpha_of(rec.w, sp3);
        B0 = fmaf(a0, B0, bp_of(a0, inp.x, xc.x)); A0 *= a0;
        B1 = fmaf(a1, B1, bp_of(a1, inp.y, xc.y)); A1 *= a1;
        B2 = fmaf(a2, B2, bp_of(a2, inp.z, xc.z)); A2 *= a2;
        B3 = fmaf(a3, B3, bp_of(a3, inp.w, xc.w)); A3 *= a3;
        base_g += TWOH;
        base_x += Hv;
    }
    const int o = ch * BH + q * 4;        // [ch][B*H] layout, coalesced
    *(float4*)&g_cA[o] = make_float4(A0, A1, A2, A3);
    *(float4*)&g_cB[o] = make_float4(B0, B1, B2, B3);
}

__global__ void scan_mid() {
    const int q = blockIdx.x * blockDim.x + threadIdx.x;  // over BH4
    if (q >= BH4) return;
    float h0 = 0.f, h1 = 0.f, h2 = 0.f, h3 = 0.f;
#pragma unroll
    for (int ch = 0; ch < NCH; ch++) {
        const int o = ch * BH + q * 4;
        *(float4*)&g_hin[o] = make_float4(h0, h1, h2, h3);
        float4 A = *(const float4*)&g_cA[o];
        float4 Bc = *(const float4*)&g_cB[o];
        h0 = fmaf(A.x, h0, Bc.x);
        h1 = fmaf(A.y, h1, Bc.y);
        h2 = fmaf(A.z, h2, Bc.z);
        h3 = fmaf(A.w, h3, Bc.w);
    }
}

// pass2: replay recurrence within chunk, fused with u = silu(z) * h
__global__ void scan_pass2(const float* __restrict__ Lambda) {
    const int gid = blockIdx.x * blockDim.x + threadIdx.x;   // over BH4*NCH
    if (gid >= BH4 * NCH) return;
    const int q  = gid % BH4;
    const int ch = gid / BH4;
    const int b = (q * 4) / Hv, c = (q * 4) % Hv;
    float4 lam = *(const float4*)&Lambda[c];
    float sp0 = log1pf(__expf(lam.x)), sp1 = log1pf(__expf(lam.y));
    float sp2 = log1pf(__expf(lam.z)), sp3 = log1pf(__expf(lam.w));
    size_t grow = (size_t)(b * Lv + ch * CHL);
    size_t base_g = grow * TWOH + c;
    size_t base_x = grow * Hv + c;
    size_t base_z = grow * TWOH + Hv + c;
    float4 h4 = *(const float4*)&g_hin[ch * BH + q * 4];
    float h0 = h4.x, h1 = h4.y, h2 = h4.z, h3 = h4.w;
#pragma unroll 4
    for (int i = 0; i < CHL; i++) {
        float4 rec = *(const float4*)&g_gates[base_g];
        float4 inp = *(const float4*)&g_gates[base_g + Hv];
        float4 xc  = *(const float4*)&g_xc[base_x];
        float a0 = alpha_of(rec.x, sp0), a1 = alpha_of(rec.y, sp1);
        float a2 = alpha_of(rec.z, sp2), a3 = alpha_of(rec.w, sp3);
        h0 = fmaf(a0, h0, bp_of(a0, inp.x, xc.x));
        h1 = fmaf(a1, h1, bp_of(a1, inp.y, xc.y));
        h2 = fmaf(a2, h2, bp_of(a2, inp.z, xc.z));
        h3 = fmaf(a3, h3, bp_of(a3, inp.w, xc.w));
        float4 z = *(const float4*)&g_xz[base_z];
        float4 u4;
        u4.x = siluf(z.x) * h0; u4.y = siluf(z.y) * h1;
        u4.z = siluf(z.z) * h2; u4.w = siluf(z.w) * h3;
        *(float4*)&g_u[base_x] = u4;
        base_g += TWOH;
        base_x += Hv;
        base_z += TWOH;
    }
}

// ---------------- add + LayerNorm (warp per token, D=256, float4) ------------
__global__ void add_ln_kernel(const float* __restrict__ a,
                              const float* __restrict__ b,
                              const float* __restrict__ gw,
                              const float* __restrict__ gb,
                              float* __restrict__ out) {
    const int warp = (blockIdx.x * blockDim.x + threadIdx.x) >> 5;
    if (warp >= Mv) return;
    const int lane = threadIdx.x & 31;
    const float* pa = a + (size_t)warp * Dv;
    const float* pb = b + (size_t)warp * Dv;
    float4 v[2];
    float s = 0.0f, s2 = 0.0f;
#pragma unroll
    for (int i = 0; i < 2; i++) {
        const int c = lane * 4 + i * 128;
        float4 va = *(const float4*)&pa[c];
        float4 vb = *(const float4*)&pb[c];
        v[i].x = va.x + vb.x; v[i].y = va.y + vb.y;
        v[i].z = va.z + vb.z; v[i].w = va.w + vb.w;
        s += v[i].x + v[i].y + v[i].z + v[i].w;
        s2 = fmaf(v[i].x, v[i].x, s2); s2 = fmaf(v[i].y, v[i].y, s2);
        s2 = fmaf(v[i].z, v[i].z, s2); s2 = fmaf(v[i].w, v[i].w, s2);
    }
#pragma unroll
    for (int o = 16; o > 0; o >>= 1) {
        s  += __shfl_xor_sync(0xffffffffu, s, o);
        s2 += __shfl_xor_sync(0xffffffffu, s2, o);
    }
    const float m = s * (1.0f / Dv);
    float var = s2 * (1.0f / Dv) - m * m;
    const float rs = rsqrtf(var + 1e-12f);
    float* po = out + (size_t)warp * Dv;
#pragma unroll
    for (int i = 0; i < 2; i++) {
        const int c = lane * 4 + i * 128;
        float4 gg = *(const float4*)&gw[c];
        float4 bb = *(const float4*)&gb[c];
        float4 o4;
        o4.x = (v[i].x - m) * rs * gg.x + bb.x;
        o4.y = (v[i].y - m) * rs * gg.y + bb.y;
        o4.z = (v[i].z - m) * rs * gg.z + bb.z;
        o4.w = (v[i].w - m) * rs * gg.w + bb.w;
        *(float4*)&po[c] = o4;
    }
}

// ---------------- launcher ---------------------------------------------------
extern "C" void kernel_launch(void* const* d_in, const int* in_sizes, int n_in,
                              void* d_out, int out_size) {
    const float* x       = (const float*)d_in[0];
    const float* w_in    = (const float*)d_in[1];
    const float* conv_w  = (const float*)d_in[2];
    const float* conv_b  = (const float*)d_in[3];
    const float* w_gates = (const float*)d_in[4];
    const float* b_gates = (const float*)d_in[5];
    const float* Lambda  = (const float*)d_in[6];
    const float* w_out   = (const float*)d_in[7];
    const float* ln1_g   = (const float*)d_in[8];
    const float* ln1_b   = (const float*)d_in[9];
    const float* ffn_w1  = (const float*)d_in[10];
    const float* ffn_b1  = (const float*)d_in[11];
    const float* ffn_w2  = (const float*)d_in[12];
    const float* ffn_b2  = (const float*)d_in[13];
    const float* ln2_g   = (const float*)d_in[14];
    const float* ln2_b   = (const float*)d_in[15];
    float* out = (float*)d_out;

    float *p_xz, *p_xc, *p_gates, *p_u, *p_y, *p_hs, *p_ff1, *p_ff;
    cudaGetSymbolAddress((void**)&p_xz, g_xz);
    cudaGetSymbolAddress((void**)&p_xc, g_xc);
    cudaGetSymbolAddress((void**)&p_gates, g_gates);
    cudaGetSymbolAddress((void**)&p_u, g_u);
    cudaGetSymbolAddress((void**)&p_y, g_y);
    cudaGetSymbolAddress((void**)&p_hs, g_hs);
    cudaGetSymbolAddress((void**)&p_ff1, g_ff1);
    cudaGetSymbolAddress((void**)&p_ff, g_ff);

    // Opt in to >48KB dynamic smem. Unconditional (no static state): cheap,
    // idempotent, host-side only.
    cudaFuncSetAttribute(gemm_tc<0>, cudaFuncAttributeMaxDynamicSharedMemorySize, GEMM_SMEM_BYTES);
    cudaFuncSetAttribute(gemm_tc<1>, cudaFuncAttributeMaxDynamicSharedMemorySize, GEMM_SMEM_BYTES);

    // 1. xz = x @ w_in                      [65536x256]@[256x1024]
    gemm_tc<0><<<dim3(TWOH / 64, Mv / 128), 256, GEMM_SMEM_BYTES>>>(x, w_in, nullptr, p_xz, Mv, TWOH, Dv);
    // 2. xc = silu(causal depthwise conv(xh) + conv_b)   (4 ch/thread)
    conv_silu_kernel<<<(Mv * (Hv / 4) + 255) / 256, 256>>>(conv_w, conv_b);
    // 3. gates = xc @ w_gates + b_gates     [65536x512]@[512x1024]
    gemm_tc<0><<<dim3(TWOH / 64, Mv / 128), 256, GEMM_SMEM_BYTES>>>(p_xc, w_gates, b_gates, p_gates, Mv, TWOH, Hv);
    // 4-6. fused alpha/beta' + chunked scan + u = silu(z)*h  (4 ch/thread)
    scan_pass1<<<(BH4 * NCH + 255) / 256, 256>>>(Lambda);
    scan_mid<<<(BH4 + 255) / 256, 256>>>();
    scan_pass2<<<(BH4 * NCH + 255) / 256, 256>>>(Lambda);
    // 7. y = u @ w_out                      [65536x512]@[512x256]
    gemm_tc<0><<<dim3(Dv / 64, Mv / 128), 256, GEMM_SMEM_BYTES>>>(p_u, w_out, nullptr, p_y, Mv, Dv, Hv);
    // 8. hs = LN1(y + x)
    add_ln_kernel<<<Mv / 8, 256>>>(p_y, x, ln1_g, ln1_b, p_hs);
    // 9. ff1 = silu(hs @ ffn_w1 + b1)       [65536x256]@[256x1024]
    gemm_tc<1><<<dim3(INNERv / 64, Mv / 128), 256, GEMM_SMEM_BYTES>>>(p_hs, ffn_w1, ffn_b1, p_ff1, Mv, INNERv, Dv);
    // 10. ff = ff1 @ ffn_w2 + b2            [65536x1024]@[1024x256]
    gemm_tc<0><<<dim3(Dv / 64, Mv / 128), 256, GEMM_SMEM_BYTES>>>(p_ff1, ffn_w2, ffn_b2, p_ff, Mv, Dv, INNERv);
    // 11. out = LN2(ff + hs)
    add_ln_kernel<<<Mv / 8, 256>>>(p_ff, p_hs, ln2_g, ln2_b, out);
}

// round 15
// speedup vs baseline: 1.7692x; 1.7692x over previous
#include <cuda_runtime.h>
#include <cuda_bf16.h>
#include <math.h>
#include <stdint.h>

// Problem constants
#define Bv     32
#define Lv     2048
#define Dv     256
#define Hv     512
#define TWOH   1024
#define INNERv 1024
#define Mv     65536      // B*L tokens
#define NCH    32         // scan chunks
#define CHL    64         // L / NCH
#define BH     (Bv * Hv)  // 16384
#define BH4    (BH / 4)   // 4096

// ---------------- scratch (static device globals; no allocation) -------------
__device__ float g_xz[67108864];    // [M, 2H]  (xh | z)
__device__ float g_xc[33554432];    // [M, H]
__device__ float g_gates[67108864]; // [M, 2H]  (rec | inp)
__device__ float g_u[33554432];     // [M, H]  silu(z)*h
__device__ float g_y[16777216];     // [M, D]
__device__ float g_hs[16777216];    // [M, D]
__device__ float g_ff1[67108864];   // [M, INNER]
__device__ float g_ff[16777216];    // [M, D]
__device__ float g_cA[524288];      // [NCH][B*H]  (coalesced layout)
__device__ float g_cB[524288];      // [NCH][B*H]
__device__ float g_hin[524288];     // [NCH][B*H]

__device__ __forceinline__ float sigmoidf_(float x) { return 1.0f / (1.0f + __expf(-x)); }
__device__ __forceinline__ float siluf(float x)     { return x / (1.0f + __expf(-x)); }

// Split two fp32 (adjacent k) into packed bf16x2 hi-pair + lo-pair.
// v ~= hi + lo to ~2^-18 relative.
__device__ __forceinline__ void split_pair(float v0, float v1,
                                           uint32_t& hp, uint32_t& lp) {
    __nv_bfloat16 h0 = __float2bfloat16_rn(v0);
    __nv_bfloat16 h1 = __float2bfloat16_rn(v1);
    float r0 = v0 - __bfloat162float(h0);
    float r1 = v1 - __bfloat162float(h1);
    __nv_bfloat162 hh = __halves2bfloat162(h0, h1);   // low = v0 (k even)
    __nv_bfloat162 ll = __halves2bfloat162(__float2bfloat16_rn(r0),
                                           __float2bfloat16_rn(r1));
    hp = *reinterpret_cast<uint32_t*>(&hh);
    lp = *reinterpret_cast<uint32_t*>(&ll);
}

__device__ __forceinline__ void mma_bf16(float* c, const uint32_t* a, const uint32_t* b) {
    asm volatile(
        "mma.sync.aligned.m16n8k16.row.col.f32.bf16.bf16.f32 "
        "{%0,%1,%2,%3}, {%4,%5,%6,%7}, {%8,%9}, {%0,%1,%2,%3};"
        : "+f"(c[0]), "+f"(c[1]), "+f"(c[2]), "+f"(c[3])
        : "r"(a[0]), "r"(a[1]), "r"(a[2]), "r"(a[3]), "r"(b[0]), "r"(b[1]));
}

// ---------------- tensor-core GEMM: C = A[MxK] @ W[KxN] (+bias, act) ---------
// 128x64 block, BK=16, 256 threads (4x2 warps), warp does 32x32 via m16n8k16.
// 3xBF16 compensated: acc += Ah*Bh + Ah*Bl + Al*Bh  (~2^-17 accuracy; validated
// error model from R12: 3xTF32 measured 2e-6 -> 3xBF16 predicted ~6e-5 < 1e-3).
// Halves MMA count and smem/LDS bytes vs 3xTF32 m16n8k8.
// Data stored as packed bf16x2 k-pairs: smem [kpair][row], 8 kpairs per K-tile.
#define SMSA 136            // A row stride (136 mod 32 == 8 -> conflict-free frag LDS)
#define SMSB 72             // B row stride
#define A_WORDS (8 * SMSA)  // 1088
#define B_WORDS (8 * SMSB)  // 576
#define STAGE_WORDS (2 * A_WORDS + 2 * B_WORDS)          // AsH, AsL, BsH, BsL = 3328
#define GEMM_SMEM_BYTES (2 * STAGE_WORDS * 4)            // 26624

template <int ACT>  // 0 = none, 1 = silu
__global__ __launch_bounds__(256, 2) void gemm_tc(const float* __restrict__ A,
                                                  const float* __restrict__ W,
                                                  const float* __restrict__ bias,
                                                  float* __restrict__ C,
                                                  int M, int N, int K) {
    extern __shared__ uint32_t smbuf[];

    const int tid  = threadIdx.x;
    const int warp = tid >> 5;
    const int lane = tid & 31;
    const int wm = warp >> 1;           // 0..3
    const int wn = warp & 1;            // 0..1
    const int m0 = blockIdx.y * 128;
    const int n0 = blockIdx.x * 64;

    float acc[2][4][4];
#pragma unroll
    for (int i = 0; i < 2; i++)
#pragma unroll
        for (int j = 0; j < 4; j++)
#pragma unroll
            for (int k = 0; k < 4; k++) acc[i][j][k] = 0.0f;

    const int ar = lane >> 2;   // 0..7 (m within fragment)
    const int ac = lane & 3;    // 0..3 (kpair within fragment)
    const int br = lane & 3;    // 0..3 (kpair)
    const int bc = lane >> 2;   // 0..7 (n)

    // Global-load mapping: A 128x16 per tile via float4; B 16x64 via 2x float2.
    const int arow = tid >> 2;            // 0..63 (second half adds 64)
    const int acol = (tid & 3) * 4;       // k: 0,4,8,12
    const int kb   = (tid & 3) * 2;       // kpair base: 0,2,4,6
    const float* Aptr = A + (size_t)(m0 + arow) * K + acol;
    const size_t Aoff1 = (size_t)64 * K;

    const int bkp   = tid >> 5;           // 0..7 (kpair)
    const int bcol2 = (tid & 31) * 2;     // 0..62
    const float* Bp0 = W + (size_t)(2 * bkp) * N + n0 + bcol2;
    const float* Bp1 = Bp0 + N;

    const int T = K >> 4;                 // number of 16-wide K tiles

    auto store_tile = [&](uint32_t* S, const float4& ca0, const float4& ca1,
                          const float2& cb0, const float2& cb1) {
        uint32_t* AsH = S;
        uint32_t* AsL = S + A_WORDS;
        uint32_t* BsH = S + 2 * A_WORDS;
        uint32_t* BsL = S + 2 * A_WORDS + B_WORDS;
        uint32_t hp, lp;
        split_pair(ca0.x, ca0.y, hp, lp);
        AsH[(kb + 0) * SMSA + arow] = hp; AsL[(kb + 0) * SMSA + arow] = lp;
        split_pair(ca0.z, ca0.w, hp, lp);
        AsH[(kb + 1) * SMSA + arow] = hp; AsL[(kb + 1) * SMSA + arow] = lp;
        split_pair(ca1.x, ca1.y, hp, lp);
        AsH[(kb + 0) * SMSA + arow + 64] = hp; AsL[(kb + 0) * SMSA + arow + 64] = lp;
        split_pair(ca1.z, ca1.w, hp, lp);
        AsH[(kb + 1) * SMSA + arow + 64] = hp; AsL[(kb + 1) * SMSA + arow + 64] = lp;
        // B: column col gets (k even, k odd) = (cb0.*, cb1.*)
        uint32_t h0, l0, h1, l1;
        split_pair(cb0.x, cb1.x, h0, l0);
        split_pair(cb0.y, cb1.y, h1, l1);
        *(uint2*)&BsH[bkp * SMSB + bcol2] = make_uint2(h0, h1);
        *(uint2*)&BsL[bkp * SMSB + bcol2] = make_uint2(l0, l1);
    };

    // Prologue: tile0 -> stage0; prefetch tile1 into regs.
    float4 pa0 = *(const float4*)(Aptr);
    float4 pa1 = *(const float4*)(Aptr + Aoff1);
    float2 pb0 = *(const float2*)(Bp0);
    float2 pb1 = *(const float2*)(Bp1);
    store_tile(smbuf, pa0, pa1, pb0, pb1);
    if (T > 1) {
        pa0 = *(const float4*)(Aptr + 16);
        pa1 = *(const float4*)(Aptr + Aoff1 + 16);
        pb0 = *(const float2*)(Bp0 + (size_t)16 * N);
        pb1 = *(const float2*)(Bp1 + (size_t)16 * N);
    }
    __syncthreads();

    for (int t = 0; t < T; t++) {
        uint32_t* S = smbuf + (t & 1) * STAGE_WORDS;
        if (t + 1 < T) {
            store_tile(smbuf + ((t + 1) & 1) * STAGE_WORDS, pa0, pa1, pb0, pb1);
            if (t + 2 < T) {
                const int koff = (t + 2) * 16;
                pa0 = *(const float4*)(Aptr + koff);
                pa1 = *(const float4*)(Aptr + Aoff1 + koff);
                pb0 = *(const float2*)(Bp0 + (size_t)koff * N);
                pb1 = *(const float2*)(Bp1 + (size_t)koff * N);
            }
        }

        const uint32_t* AsH = S;
        const uint32_t* AsL = S + A_WORDS;
        const uint32_t* BsH = S + 2 * A_WORDS;
        const uint32_t* BsL = S + 2 * A_WORDS + B_WORDS;

        uint32_t aH[2][4], aL[2][4];
#pragma unroll
        for (int mt = 0; mt < 2; mt++) {
            const int rb = wm * 32 + mt * 16 + ar;
            aH[mt][0] = AsH[ac * SMSA + rb];
            aH[mt][1] = AsH[ac * SMSA + rb + 8];
            aH[mt][2] = AsH[(ac + 4) * SMSA + rb];
            aH[mt][3] = AsH[(ac + 4) * SMSA + rb + 8];
            aL[mt][0] = AsL[ac * SMSA + rb];
            aL[mt][1] = AsL[ac * SMSA + rb + 8];
            aL[mt][2] = AsL[(ac + 4) * SMSA + rb];
            aL[mt][3] = AsL[(ac + 4) * SMSA + rb + 8];
        }
        uint32_t bH[4][2], bL[4][2];
#pragma unroll
        for (int nt = 0; nt < 4; nt++) {
            const int col = wn * 32 + nt * 8 + bc;
            bH[nt][0] = BsH[br * SMSB + col];
            bH[nt][1] = BsH[(br + 4) * SMSB + col];
            bL[nt][0] = BsL[br * SMSB + col];
            bL[nt][1] = BsL[(br + 4) * SMSB + col];
        }
#pragma unroll
        for (int mt = 0; mt < 2; mt++)
#pragma unroll
            for (int nt = 0; nt < 4; nt++) {
                mma_bf16(acc[mt][nt], aH[mt], bH[nt]);
                mma_bf16(acc[mt][nt], aH[mt], bL[nt]);
                mma_bf16(acc[mt][nt], aL[mt], bH[nt]);
            }
        __syncthreads();
    }

    // Epilogue: c0,c1 -> (row, col..col+1), c2,c3 -> (row+8, col..col+1)
#pragma unroll
    for (int mt = 0; mt < 2; mt++) {
#pragma unroll
        for (int nt = 0; nt < 4; nt++) {
            const int row = m0 + wm * 32 + mt * 16 + (lane >> 2);
            const int col = n0 + wn * 32 + nt * 8 + (lane & 3) * 2;
            float b0 = 0.f, b1 = 0.f;
            if (bias) { b0 = bias[col]; b1 = bias[col + 1]; }
            float v0 = acc[mt][nt][0] + b0;
            float v1 = acc[mt][nt][1] + b1;
            float v2 = acc[mt][nt][2] + b0;
            float v3 = acc[mt][nt][3] + b1;
            if (ACT == 1) { v0 = siluf(v0); v1 = siluf(v1); v2 = siluf(v2); v3 = siluf(v3); }
            *(float2*)&C[(size_t)row * N + col]       = make_float2(v0, v1);
            *(float2*)&C[(size_t)(row + 8) * N + col] = make_float2(v2, v3);
        }
    }
}

// ------- depthwise causal conv (K=4) + bias + silu, 4 channels/thread --------
__global__ void conv_silu_kernel(const float* __restrict__ conv_w,
                                 const float* __restrict__ conv_b) {
    size_t idx = (size_t)blockIdx.x * blockDim.x + threadIdx.x;   // over M*H/4
    if (idx >= (size_t)Mv * Hv / 4) return;
    const int c = (int)((idx * 4) % Hv);          // channel base (multiple of 4)
    const size_t row = (idx * 4) / Hv;            // b*L + t
    const int t = (int)(row % Lv);

    float4 w0 = *(const float4*)&conv_w[(c + 0) * 4];
    float4 w1 = *(const float4*)&conv_w[(c + 1) * 4];
    float4 w2 = *(const float4*)&conv_w[(c + 2) * 4];
    float4 w3 = *(const float4*)&conv_w[(c + 3) * 4];
    float4 bb = *(const float4*)&conv_b[c];
    float a0 = bb.x, a1 = bb.y, a2 = bb.z, a3 = bb.w;

#pragma unroll
    for (int j = 0; j < 4; j++) {
        const int tt = t - 3 + j;
        if (tt >= 0) {
            float4 xv = *(const float4*)&g_xz[(row - 3 + j) * TWOH + c];
            a0 = fmaf(((const float*)&w0)[j], xv.x, a0);
            a1 = fmaf(((const float*)&w1)[j], xv.y, a1);
            a2 = fmaf(((const float*)&w2)[j], xv.z, a2);
            a3 = fmaf(((const float*)&w3)[j], xv.w, a3);
        }
    }
    float4 o;
    o.x = siluf(a0); o.y = siluf(a1); o.z = siluf(a2); o.w = siluf(a3);
    *(float4*)&g_xc[row * Hv + c] = o;
}

// ---------------- fused alpha/beta' + chunked scan (4 ch/thread) -------------
__device__ __forceinline__ float alpha_of(float rec, float sp) {
    return __expf(-sp * sigmoidf_(rec));
}
__device__ __forceinline__ float bp_of(float alpha, float inp, float xc) {
    return sqrtf(1.0f - alpha * alpha + 1e-8f) * sigmoidf_(inp) * xc;
}

__global__ void scan_pass1(const float* __restrict__ Lambda) {
    const int gid = blockIdx.x * blockDim.x + threadIdx.x;   // over BH4*NCH
    if (gid >= BH4 * NCH) return;
    const int q  = gid % BH4;          // 4-channel group within B*H
    const int ch = gid / BH4;
    const int b = (q * 4) / Hv, c = (q * 4) % Hv;
    float4 lam = *(const float4*)&Lambda[c];
    float sp0 = log1pf(__expf(lam.x)), sp1 = log1pf(__expf(lam.y));
    float sp2 = log1pf(__expf(lam.z)), sp3 = log1pf(__expf(lam.w));
    size_t grow = (size_t)(b * Lv + ch * CHL);
    size_t base_g = grow * TWOH + c;
    size_t base_x = grow * Hv + c;
    float A0 = 1.f, A1 = 1.f, A2 = 1.f, A3 = 1.f;
    float B0 = 0.f, B1 = 0.f, B2 = 0.f, B3 = 0.f;
#pragma unroll 4
    for (int i = 0; i < CHL; i++) {
        float4 rec = *(const float4*)&g_gates[base_g];
        float4 inp = *(const float4*)&g_gates[base_g + Hv];
        float4 xc  = *(const float4*)&g_xc[base_x];
        float a0 = alpha_of(rec.x, sp0), a1 = alpha_of(rec.y, sp1);
        float a2 = alpha_of(rec.z, sp2), a3 = alpha_of(rec.w, sp3);
        B0 = fmaf(a0, B0, bp_of(a0, inp.x, xc.x)); A0 *= a0;
        B1 = fmaf(a1, B1, bp_of(a1, inp.y, xc.y)); A1 *= a1;
        B2 = fmaf(a2, B2, bp_of(a2, inp.z, xc.z)); A2 *= a2;
        B3 = fmaf(a3, B3, bp_of(a3, inp.w, xc.w)); A3 *= a3;
        base_g += TWOH;
        base_x += Hv;
    }
    const int o = ch * BH + q * 4;        // [ch][B*H] layout, coalesced
    *(float4*)&g_cA[o] = make_float4(A0, A1, A2, A3);
    *(float4*)&g_cB[o] = make_float4(B0, B1, B2, B3);
}

__global__ void scan_mid() {
    const int q = blockIdx.x * blockDim.x + threadIdx.x;  // over BH4
    if (q >= BH4) return;
    float h0 = 0.f, h1 = 0.f, h2 = 0.f, h3 = 0.f;
#pragma unroll
    for (int ch = 0; ch < NCH; ch++) {
        const int o = ch * BH + q * 4;
        *(float4*)&g_hin[o] = make_float4(h0, h1, h2, h3);
        float4 A = *(const float4*)&g_cA[o];
        float4 Bc = *(const float4*)&g_cB[o];
        h0 = fmaf(A.x, h0, Bc.x);
        h1 = fmaf(A.y, h1, Bc.y);
        h2 = fmaf(A.z, h2, Bc.z);
        h3 = fmaf(A.w, h3, Bc.w);
    }
}

// pass2: replay recurrence within chunk, fused with u = silu(z) * h
__global__ void scan_pass2(const float* __restrict__ Lambda) {
    const int gid = blockIdx.x * blockDim.x + threadIdx.x;   // over BH4*NCH
    if (gid >= BH4 * NCH) return;
    const int q  = gid % BH4;
    const int ch = gid / BH4;
    const int b = (q * 4) / Hv, c = (q * 4) % Hv;
    float4 lam = *(const float4*)&Lambda[c];
    float sp0 = log1pf(__expf(lam.x)), sp1 = log1pf(__expf(lam.y));
    float sp2 = log1pf(__expf(lam.z)), sp3 = log1pf(__expf(lam.w));
    size_t grow = (size_t)(b * Lv + ch * CHL);
    size_t base_g = grow * TWOH + c;
    size_t base_x = grow * Hv + c;
    size_t base_z = grow * TWOH + Hv + c;
    float4 h4 = *(const float4*)&g_hin[ch * BH + q * 4];
    float h0 = h4.x, h1 = h4.y, h2 = h4.z, h3 = h4.w;
#pragma unroll 4
    for (int i = 0; i < CHL; i++) {
        float4 rec = *(const float4*)&g_gates[base_g];
        float4 inp = *(const float4*)&g_gates[base_g + Hv];
        float4 xc  = *(const float4*)&g_xc[base_x];
        float a0 = alpha_of(rec.x, sp0), a1 = alpha_of(rec.y, sp1);
        float a2 = alpha_of(rec.z, sp2), a3 = alpha_of(rec.w, sp3);
        h0 = fmaf(a0, h0, bp_of(a0, inp.x, xc.x));
        h1 = fmaf(a1, h1, bp_of(a1, inp.y, xc.y));
        h2 = fmaf(a2, h2, bp_of(a2, inp.z, xc.z));
        h3 = fmaf(a3, h3, bp_of(a3, inp.w, xc.w));
        float4 z = *(const float4*)&g_xz[base_z];
        float4 u4;
        u4.x = siluf(z.x) * h0; u4.y = siluf(z.y) * h1;
        u4.z = siluf(z.z) * h2; u4.w = siluf(z.w) * h3;
        *(float4*)&g_u[base_x] = u4;
        base_g += TWOH;
        base_x += Hv;
        base_z += TWOH;
    }
}

// ---------------- add + LayerNorm (warp per token, D=256, float4) ------------
__global__ void add_ln_kernel(const float* __restrict__ a,
                              const float* __restrict__ b,
                              const float* __restrict__ gw,
                              const float* __restrict__ gb,
                              float* __restrict__ out) {
    const int warp = (blockIdx.x * blockDim.x + threadIdx.x) >> 5;
    if (warp >= Mv) return;
    const int lane = threadIdx.x & 31;
    const float* pa = a + (size_t)warp * Dv;
    const float* pb = b + (size_t)warp * Dv;
    float4 v[2];
    float s = 0.0f, s2 = 0.0f;
#pragma unroll
    for (int i = 0; i < 2; i++) {
        const int c = lane * 4 + i * 128;
        float4 va = *(const float4*)&pa[c];
        float4 vb = *(const float4*)&pb[c];
        v[i].x = va.x + vb.x; v[i].y = va.y + vb.y;
        v[i].z = va.z + vb.z; v[i].w = va.w + vb.w;
        s += v[i].x + v[i].y + v[i].z + v[i].w;
        s2 = fmaf(v[i].x, v[i].x, s2); s2 = fmaf(v[i].y, v[i].y, s2);
        s2 = fmaf(v[i].z, v[i].z, s2); s2 = fmaf(v[i].w, v[i].w, s2);
    }
#pragma unroll
    for (int o = 16; o > 0; o >>= 1) {
        s  += __shfl_xor_sync(0xffffffffu, s, o);
        s2 += __shfl_xor_sync(0xffffffffu, s2, o);
    }
    const float m = s * (1.0f / Dv);
    float var = s2 * (1.0f / Dv) - m * m;
    const float rs = rsqrtf(var + 1e-12f);
    float* po = out + (size_t)warp * Dv;
#pragma unroll
    for (int i = 0; i < 2; i++) {
        const int c = lane * 4 + i * 128;
        float4 gg = *(const float4*)&gw[c];
        float4 bb = *(const float4*)&gb[c];
        float4 o4;
        o4.x = (v[i].x - m) * rs * gg.x + bb.x;
        o4.y = (v[i].y - m) * rs * gg.y + bb.y;
        o4.z = (v[i].z - m) * rs * gg.z + bb.z;
        o4.w = (v[i].w - m) * rs * gg.w + bb.w;
        *(float4*)&po[c] = o4;
    }
}

// ---------------- launcher ---------------------------------------------------
extern "C" void kernel_launch(void* const* d_in, const int* in_sizes, int n_in,
                              void* d_out, int out_size) {
    const float* x       = (const float*)d_in[0];
    const float* w_in    = (const float*)d_in[1];
    const float* conv_w  = (const float*)d_in[2];
    const float* conv_b  = (const float*)d_in[3];
    const float* w_gates = (const float*)d_in[4];
    const float* b_gates = (const float*)d_in[5];
    const float* Lambda  = (const float*)d_in[6];
    const float* w_out   = (const float*)d_in[7];
    const float* ln1_g   = (const float*)d_in[8];
    const float* ln1_b   = (const float*)d_in[9];
    const float* ffn_w1  = (const float*)d_in[10];
    const float* ffn_b1  = (const float*)d_in[11];
    const float* ffn_w2  = (const float*)d_in[12];
    const float* ffn_b2  = (const float*)d_in[13];
    const float* ln2_g   = (const float*)d_in[14];
    const float* ln2_b   = (const float*)d_in[15];
    float* out = (float*)d_out;

    float *p_xz, *p_xc, *p_gates, *p_u, *p_y, *p_hs, *p_ff1, *p_ff;
    cudaGetSymbolAddress((void**)&p_xz, g_xz);
    cudaGetSymbolAddress((void**)&p_xc, g_xc);
    cudaGetSymbolAddress((void**)&p_gates, g_gates);
    cudaGetSymbolAddress((void**)&p_u, g_u);
    cudaGetSymbolAddress((void**)&p_y, g_y);
    cudaGetSymbolAddress((void**)&p_hs, g_hs);
    cudaGetSymbolAddress((void**)&p_ff1, g_ff1);
    cudaGetSymbolAddress((void**)&p_ff, g_ff);

    cudaFuncSetAttribute(gemm_tc<0>, cudaFuncAttributeMaxDynamicSharedMemorySize, GEMM_SMEM_BYTES);
    cudaFuncSetAttribute(gemm_tc<1>, cudaFuncAttributeMaxDynamicSharedMemorySize, GEMM_SMEM_BYTES);

    // 1. xz = x @ w_in                      [65536x256]@[256x1024]
    gemm_tc<0><<<dim3(TWOH / 64, Mv / 128), 256, GEMM_SMEM_BYTES>>>(x, w_in, nullptr, p_xz, Mv, TWOH, Dv);
    // 2. xc = silu(causal depthwise conv(xh) + conv_b)   (4 ch/thread)
    conv_silu_kernel<<<(Mv * (Hv / 4) + 255) / 256, 256>>>(conv_w, conv_b);
    // 3. gates = xc @ w_gates + b_gates     [65536x512]@[512x1024]
    gemm_tc<0><<<dim3(TWOH / 64, Mv / 128), 256, GEMM_SMEM_BYTES>>>(p_xc, w_gates, b_gates, p_gates, Mv, TWOH, Hv);
    // 4-6. fused alpha/beta' + chunked scan + u = silu(z)*h  (4 ch/thread)
    scan_pass1<<<(BH4 * NCH + 255) / 256, 256>>>(Lambda);
    scan_mid<<<(BH4 + 255) / 256, 256>>>();
    scan_pass2<<<(BH4 * NCH + 255) / 256, 256>>>(Lambda);
    // 7. y = u @ w_out                      [65536x512]@[512x256]
    gemm_tc<0><<<dim3(Dv / 64, Mv / 128), 256, GEMM_SMEM_BYTES>>>(p_u, w_out, nullptr, p_y, Mv, Dv, Hv);
    // 8. hs = LN1(y + x)
    add_ln_kernel<<<Mv / 8, 256>>>(p_y, x, ln1_g, ln1_b, p_hs);
    // 9. ff1 = silu(hs @ ffn_w1 + b1)       [65536x256]@[256x1024]
    gemm_tc<1><<<dim3(INNERv / 64, Mv / 128), 256, GEMM_SMEM_BYTES>>>(p_hs, ffn_w1, ffn_b1, p_ff1, Mv, INNERv, Dv);
    // 10. ff = ff1 @ ffn_w2 + b2            [65536x1024]@[1024x256]
    gemm_tc<0><<<dim3(Dv / 64, Mv / 128), 256, GEMM_SMEM_BYTES>>>(p_ff1, ffn_w2, ffn_b2, p_ff, Mv, Dv, INNERv);
    // 11. out = LN2(ff + hs)
    add_ln_kernel<<<Mv / 8, 256>>>(p_ff, p_hs, ln2_g, ln2_b, out);
}